// round 1
// baseline (speedup 1.0000x reference)
#include <cuda_runtime.h>
#include <math_constants.h>

#define BB 4
#define TT 4096
#define DD 1024
#define HH 64
#define NROW (BB*TT)

// Scratch for projected k, q, v  (4 MB each) — __device__ globals per allocation rules.
__device__ float g_K[NROW*HH];
__device__ float g_Q[NROW*HH];
__device__ float g_V[NROW*HH];

__device__ __forceinline__ float grpmax16(float v) {
#pragma unroll
    for (int m = 8; m >= 1; m >>= 1)
        v = fmaxf(v, __shfl_xor_sync(0xffffffffu, v, m));
    return v;
}
__device__ __forceinline__ float grpsum16(float v) {
#pragma unroll
    for (int m = 8; m >= 1; m >>= 1)
        v += __shfl_xor_sync(0xffffffffu, v, m);
    return v;
}

// 4x4 outer product accumulate
__device__ __forceinline__ void op4(float (&acc)[4][4], float4 a, float4 b) {
    acc[0][0] = fmaf(a.x, b.x, acc[0][0]); acc[0][1] = fmaf(a.x, b.y, acc[0][1]);
    acc[0][2] = fmaf(a.x, b.z, acc[0][2]); acc[0][3] = fmaf(a.x, b.w, acc[0][3]);
    acc[1][0] = fmaf(a.y, b.x, acc[1][0]); acc[1][1] = fmaf(a.y, b.y, acc[1][1]);
    acc[1][2] = fmaf(a.y, b.z, acc[1][2]); acc[1][3] = fmaf(a.y, b.w, acc[1][3]);
    acc[2][0] = fmaf(a.z, b.x, acc[2][0]); acc[2][1] = fmaf(a.z, b.y, acc[2][1]);
    acc[2][2] = fmaf(a.z, b.z, acc[2][2]); acc[2][3] = fmaf(a.z, b.w, acc[2][3]);
    acc[3][0] = fmaf(a.w, b.x, acc[3][0]); acc[3][1] = fmaf(a.w, b.y, acc[3][1]);
    acc[3][2] = fmaf(a.w, b.z, acc[3][2]); acc[3][3] = fmaf(a.w, b.w, acc[3][3]);
}

// ---------------------------------------------------------------------------
// QKV projection: out = x @ W + b for (k,q,v) selected by blockIdx.y.
// CTA tile: 64 rows x 64 cols, K chunked by 64. X chunk stored transposed +
// XOR-swizzled (slot = (t>>2) ^ (k>>2)) so compute reads are conflict-free.
// ---------------------------------------------------------------------------
__global__ __launch_bounds__(256)
void qkv_kernel(const float* __restrict__ x,
                const float* __restrict__ Wk, const float* __restrict__ bk,
                const float* __restrict__ Wq, const float* __restrict__ bq,
                const float* __restrict__ Wv, const float* __restrict__ bv)
{
    __shared__ float Xst[64][64];   // transposed+swizzled: (k, t)
    __shared__ float Ws [64][64];   // (k, n) natural

    const float* W; const float* bias; float* out;
    if (blockIdx.y == 0)      { W = Wk; bias = bk; out = g_K; }
    else if (blockIdx.y == 1) { W = Wq; bias = bq; out = g_Q; }
    else                      { W = Wv; bias = bv; out = g_V; }

    const int tid = threadIdx.x;
    const int tx = tid & 15, ty = tid >> 4;
    const int row0 = blockIdx.x * 64;

    float acc[4][4] = {};

    for (int k0 = 0; k0 < DD; k0 += 64) {
        __syncthreads();
#pragma unroll
        for (int u = 0; u < 4; u++) {
            int sid = tid + 256 * u;
            int r = sid >> 4, c4 = sid & 15;
            float4 v = *(const float4*)(x + (size_t)(row0 + r) * DD + k0 + 4 * c4);
            int col = 4 * ((r >> 2) ^ c4) + (r & 3);
            Xst[4 * c4 + 0][col] = v.x;
            Xst[4 * c4 + 1][col] = v.y;
            Xst[4 * c4 + 2][col] = v.z;
            Xst[4 * c4 + 3][col] = v.w;
            float4 w = *(const float4*)(W + (size_t)(k0 + r) * HH + 4 * c4);
            *(float4*)&Ws[r][4 * c4] = w;
        }
        __syncthreads();
#pragma unroll 1
        for (int h4 = 0; h4 < 16; h4++) {
            const float* ap = &Xst[4 * h4][4 * (ty ^ h4)];
            const float* bp = &Ws [4 * h4][4 * tx];
#pragma unroll
            for (int kk = 0; kk < 4; kk++) {
                float4 a = *(const float4*)(ap + kk * 64);
                float4 b = *(const float4*)(bp + kk * 64);
                op4(acc, a, b);
            }
        }
    }
    float4 bb = *(const float4*)(bias + 4 * tx);
#pragma unroll
    for (int i = 0; i < 4; i++) {
        float4 o;
        o.x = acc[i][0] + bb.x; o.y = acc[i][1] + bb.y;
        o.z = acc[i][2] + bb.z; o.w = acc[i][3] + bb.w;
        *(float4*)(out + (size_t)(row0 + 4 * ty + i) * HH + 4 * tx) = o;
    }
}

// ---------------------------------------------------------------------------
// Causal flash attention, fp32. Scores S[t][s] = k[t]·q[s] * 1/8 (note: k is
// the "query" per the reference's k @ q^T). Online softmax, 64x64 tiles.
// Each CTA processes TWO row-tiles (bt, 63-bt) -> uniform 65 tile-units.
// ---------------------------------------------------------------------------
__global__ __launch_bounds__(256)
void attn_kernel(float* __restrict__ out)
{
    __shared__ float Kst[64][64];  // transposed+swizzled k-tile (h, t)
    __shared__ float QP [64][64];  // transposed+swizzled q-tile (h, s); reused as P^T (s, t)
    __shared__ float Vs [64][64];  // natural (s, h)

    const int tid = threadIdx.x;
    const int tx = tid & 15, ty = tid >> 4;
    const int b = blockIdx.y;
    const int jj = blockIdx.x;          // 0..31

#pragma unroll 1
    for (int half = 0; half < 2; half++) {
        const int bt = half ? jj : (63 - jj);
        const size_t rowbase = (size_t)b * TT + (size_t)bt * 64;

        __syncthreads();   // protect Kst/QP/Vs against previous half's readers
#pragma unroll
        for (int u = 0; u < 4; u++) {
            int sid = tid + 256 * u;
            int r = sid >> 4, c4 = sid & 15;
            float4 v = *(const float4*)(g_K + (rowbase + r) * HH + 4 * c4);
            int col = 4 * ((r >> 2) ^ c4) + (r & 3);
            Kst[4 * c4 + 0][col] = v.x;
            Kst[4 * c4 + 1][col] = v.y;
            Kst[4 * c4 + 2][col] = v.z;
            Kst[4 * c4 + 3][col] = v.w;
        }

        float acc[4][4] = {};
        float mrow[4] = { -CUDART_INF_F, -CUDART_INF_F, -CUDART_INF_F, -CUDART_INF_F };
        float lrow[4] = {};

        for (int st = 0; st <= bt; st++) {
            const size_t colbase = (size_t)b * TT + (size_t)st * 64;
            __syncthreads();   // previous O-gemm done with QP/Vs; Kst visible on first iter
#pragma unroll
            for (int u = 0; u < 4; u++) {
                int sid = tid + 256 * u;
                int r = sid >> 4, c4 = sid & 15;
                float4 v = *(const float4*)(g_Q + (colbase + r) * HH + 4 * c4);
                int col = 4 * ((r >> 2) ^ c4) + (r & 3);
                QP[4 * c4 + 0][col] = v.x;
                QP[4 * c4 + 1][col] = v.y;
                QP[4 * c4 + 2][col] = v.z;
                QP[4 * c4 + 3][col] = v.w;
                float4 w = *(const float4*)(g_V + (colbase + r) * HH + 4 * c4);
                *(float4*)&Vs[r][4 * c4] = w;
            }
            __syncthreads();

            // ---- S = Kst^T(Q-role) x QP: outer product over h ----
            float s[4][4] = {};
#pragma unroll 1
            for (int h4 = 0; h4 < 16; h4++) {
                const float* kp = &Kst[4 * h4][4 * (ty ^ h4)];
                const float* qp = &QP [4 * h4][4 * (tx ^ h4)];
#pragma unroll
                for (int kk = 0; kk < 4; kk++) {
                    float4 a = *(const float4*)(kp + kk * 64);
                    float4 c = *(const float4*)(qp + kk * 64);
                    op4(s, a, c);
                }
            }

            const float scale = 0.125f;   // 1/sqrt(64)
            if (st == bt) {
#pragma unroll
                for (int i = 0; i < 4; i++)
#pragma unroll
                    for (int j2 = 0; j2 < 4; j2++) {
                        int r = 4 * ty + i, c = 4 * tx + j2;
                        s[i][j2] = (c <= r) ? s[i][j2] * scale : -1e30f;
                    }
            } else {
#pragma unroll
                for (int i = 0; i < 4; i++)
#pragma unroll
                    for (int j2 = 0; j2 < 4; j2++)
                        s[i][j2] *= scale;
            }

            // ---- online softmax (per row, reduced across the 16 tx lanes) ----
#pragma unroll
            for (int i = 0; i < 4; i++) {
                float rm = fmaxf(fmaxf(s[i][0], s[i][1]), fmaxf(s[i][2], s[i][3]));
                rm = grpmax16(rm);
                float mnew = fmaxf(mrow[i], rm);
                float corr = __expf(mrow[i] - mnew);   // exp(-inf)=0 on first tile
                mrow[i] = mnew;
                float rs = 0.f;
#pragma unroll
                for (int j2 = 0; j2 < 4; j2++) {
                    s[i][j2] = __expf(s[i][j2] - mnew);
                    rs += s[i][j2];
                }
                rs = grpsum16(rs);
                lrow[i] = lrow[i] * corr + rs;
                acc[i][0] *= corr; acc[i][1] *= corr;
                acc[i][2] *= corr; acc[i][3] *= corr;
            }

            __syncthreads();   // all S-gemm reads of QP done
            // ---- store P^T into QP: element (s,t) at slot (t>>2)^(s>>2) ----
#pragma unroll
            for (int j2 = 0; j2 < 4; j2++) {
                int prow = 4 * tx + j2;
                int col = 4 * (ty ^ tx);
                QP[prow][col + 0] = s[0][j2];
                QP[prow][col + 1] = s[1][j2];
                QP[prow][col + 2] = s[2][j2];
                QP[prow][col + 3] = s[3][j2];
            }
            __syncthreads();

            // ---- O += P x V: outer product over s ----
#pragma unroll 1
            for (int s4 = 0; s4 < 16; s4++) {
                const float* pp = &QP[4 * s4][4 * (ty ^ s4)];
                const float* vp = &Vs[4 * s4][4 * tx];
#pragma unroll
                for (int kk = 0; kk < 4; kk++) {
                    float4 p = *(const float4*)(pp + kk * 64);
                    float4 v = *(const float4*)(vp + kk * 64);
                    op4(acc, p, v);
                }
            }
        }

        // ---- normalize and write ----
#pragma unroll
        for (int i = 0; i < 4; i++) {
            float inv = 1.0f / lrow[i];
            float4 o;
            o.x = acc[i][0] * inv; o.y = acc[i][1] * inv;
            o.z = acc[i][2] * inv; o.w = acc[i][3] * inv;
            *(float4*)(out + (rowbase + 4 * ty + i) * HH + 4 * tx) = o;
        }
    }
}

extern "C" void kernel_launch(void* const* d_in, const int* in_sizes, int n_in,
                              void* d_out, int out_size)
{
    const float* x  = (const float*)d_in[0];
    const float* Wk = (const float*)d_in[1];
    const float* bk = (const float*)d_in[2];
    const float* Wq = (const float*)d_in[3];
    const float* bq = (const float*)d_in[4];
    const float* Wv = (const float*)d_in[5];
    const float* bv = (const float*)d_in[6];
    float* out = (float*)d_out;

    dim3 g1(NROW / 64, 3);    // 256 row-tiles x {k,q,v}
    qkv_kernel<<<g1, 256>>>(x, Wk, bk, Wq, bq, Wv, bv);

    dim3 g2(32, BB);          // paired row-tiles: uniform work per CTA
    attn_kernel<<<g2, 256>>>(out);
}

// round 2
// speedup vs baseline: 1.0387x; 1.0387x over previous
#include <cuda_runtime.h>
#include <math_constants.h>

#define BB 4
#define TT 4096
#define DD 1024
#define HH 64
#define NROW (BB*TT)

typedef unsigned long long ull;

// Scratch for projected k, q, v — __device__ globals per allocation rules.
__device__ float g_K[NROW*HH];
__device__ float g_Q[NROW*HH];
__device__ float g_V[NROW*HH];

// ---- packed f32x2 helpers (ptxas never emits these from C++) ----
__device__ __forceinline__ ull pack2(float lo, float hi) {
    ull r; asm("mov.b64 %0, {%1,%2};" : "=l"(r) : "f"(lo), "f"(hi)); return r;
}
__device__ __forceinline__ void unpack2(ull v, float& lo, float& hi) {
    asm("mov.b64 {%0,%1}, %2;" : "=f"(lo), "=f"(hi) : "l"(v));
}
__device__ __forceinline__ void ffma2(ull& d, ull a, ull b) {
    asm("fma.rn.f32x2 %0, %1, %2, %0;" : "+l"(d) : "l"(a), "l"(b));
}
__device__ __forceinline__ void mul2(ull& d, ull a) {
    asm("mul.rn.f32x2 %0, %0, %1;" : "+l"(d) : "l"(a));
}

__device__ __forceinline__ float grpmax16(float v) {
#pragma unroll
    for (int m = 8; m >= 1; m >>= 1)
        v = fmaxf(v, __shfl_xor_sync(0xffffffffu, v, m));
    return v;
}
__device__ __forceinline__ float grpsum16(float v) {
#pragma unroll
    for (int m = 8; m >= 1; m >>= 1)
        v += __shfl_xor_sync(0xffffffffu, v, m);
    return v;
}

// ---------------------------------------------------------------------------
// QKV projection: out = x @ W + b. 64x64 CTA tile, 256 threads, micro 4x4,
// rows packed in f32x2 pairs. X chunk transposed + XOR-swizzled.
// ---------------------------------------------------------------------------
__global__ __launch_bounds__(256)
void qkv_kernel(const float* __restrict__ x,
                const float* __restrict__ Wk, const float* __restrict__ bk,
                const float* __restrict__ Wq, const float* __restrict__ bq,
                const float* __restrict__ Wv, const float* __restrict__ bv)
{
    __shared__ float Xst[64][64];   // transposed+swizzled: (k, t)
    __shared__ float Ws [64][64];   // (k, n) natural

    const float* W; const float* bias; float* out;
    if (blockIdx.y == 0)      { W = Wk; bias = bk; out = g_K; }
    else if (blockIdx.y == 1) { W = Wq; bias = bq; out = g_Q; }
    else                      { W = Wv; bias = bv; out = g_V; }

    const int tid = threadIdx.x;
    const int tx = tid & 15, ty = tid >> 4;
    const int row0 = blockIdx.x * 64;

    ull acc2[2][4];                 // rows (4ty+2p, 4ty+2p+1), cols 4tx+j
#pragma unroll
    for (int p = 0; p < 2; p++)
#pragma unroll
        for (int j = 0; j < 4; j++) acc2[p][j] = pack2(0.f, 0.f);

    for (int k0 = 0; k0 < DD; k0 += 64) {
        __syncthreads();
#pragma unroll
        for (int u = 0; u < 4; u++) {
            int sid = tid + 256 * u;
            int r = sid >> 4, c4 = sid & 15;
            float4 v = *(const float4*)(x + (size_t)(row0 + r) * DD + k0 + 4 * c4);
            int col = 4 * ((r >> 2) ^ c4) + (r & 3);
            Xst[4 * c4 + 0][col] = v.x;
            Xst[4 * c4 + 1][col] = v.y;
            Xst[4 * c4 + 2][col] = v.z;
            Xst[4 * c4 + 3][col] = v.w;
            float4 w = *(const float4*)(W + (size_t)(k0 + r) * HH + 4 * c4);
            *(float4*)&Ws[r][4 * c4] = w;
        }
        __syncthreads();
#pragma unroll 1
        for (int k4 = 0; k4 < 16; k4++) {
            const float* ap = &Xst[4 * k4][4 * (ty ^ k4)];
            const float* bp = &Ws [4 * k4][4 * tx];
#pragma unroll
            for (int kk = 0; kk < 4; kk++) {
                ulonglong2 A = *(const ulonglong2*)(ap + kk * 64);
                float4 b = *(const float4*)(bp + kk * 64);
                ull b0 = pack2(b.x, b.x), b1 = pack2(b.y, b.y);
                ull b2 = pack2(b.z, b.z), b3 = pack2(b.w, b.w);
                ffma2(acc2[0][0], A.x, b0); ffma2(acc2[0][1], A.x, b1);
                ffma2(acc2[0][2], A.x, b2); ffma2(acc2[0][3], A.x, b3);
                ffma2(acc2[1][0], A.y, b0); ffma2(acc2[1][1], A.y, b1);
                ffma2(acc2[1][2], A.y, b2); ffma2(acc2[1][3], A.y, b3);
            }
        }
    }
    float4 bb = *(const float4*)(bias + 4 * tx);
    float a[4][4];
#pragma unroll
    for (int p = 0; p < 2; p++)
#pragma unroll
        for (int j = 0; j < 4; j++) unpack2(acc2[p][j], a[2*p][j], a[2*p+1][j]);
#pragma unroll
    for (int i = 0; i < 4; i++) {
        float4 o;
        o.x = a[i][0] + bb.x; o.y = a[i][1] + bb.y;
        o.z = a[i][2] + bb.z; o.w = a[i][3] + bb.w;
        *(float4*)(out + (size_t)(row0 + 4 * ty + i) * HH + 4 * tx) = o;
    }
}

// ---------------------------------------------------------------------------
// Causal flash attention, fp32, f32x2 packed. 64x64 tiles, 128 threads,
// per-thread micro 8 rows x 4 cols (rows packed in pairs).
// 256 CTAs launched in DESCENDING work order -> LPT via CLC work-stealing.
// ---------------------------------------------------------------------------
__global__ __launch_bounds__(128)
void attn_kernel(float* __restrict__ out)
{
    __shared__ float Kst[64][64];  // transposed+swizzled k-tile (h, t)
    __shared__ float QP [64][64];  // transposed+swizzled q-tile (h, s); reused as P^T (s, t)
    __shared__ float Vs [64][64];  // natural (s, h)

    const int tid = threadIdx.x;
    const int tx = tid & 15, ty = tid >> 4;       // ty 0..7 -> rows 8ty..8ty+7
    const int bid = blockIdx.x;
    const int b  = bid & 3;
    const int bt = 63 - (bid >> 2);               // descending work order
    const size_t rowbase = (size_t)b * TT + (size_t)bt * 64;

    // load K row-tile (transposed + swizzled)
#pragma unroll
    for (int u = 0; u < 8; u++) {
        int sid = tid + 128 * u;
        int r = sid >> 4, c4 = sid & 15;
        float4 v = *(const float4*)(g_K + (rowbase + r) * HH + 4 * c4);
        int col = 4 * ((r >> 2) ^ c4) + (r & 3);
        Kst[4 * c4 + 0][col] = v.x;
        Kst[4 * c4 + 1][col] = v.y;
        Kst[4 * c4 + 2][col] = v.z;
        Kst[4 * c4 + 3][col] = v.w;
    }

    ull o2[4][4];                                  // O acc: row-pairs x 4 cols
    ull zz = pack2(0.f, 0.f);
#pragma unroll
    for (int p = 0; p < 4; p++)
#pragma unroll
        for (int j = 0; j < 4; j++) o2[p][j] = zz;
    float mrow[8], lrow[8];
#pragma unroll
    for (int i = 0; i < 8; i++) { mrow[i] = -CUDART_INF_F; lrow[i] = 0.f; }

    for (int st = 0; st <= bt; st++) {
        const size_t colbase = (size_t)b * TT + (size_t)st * 64;
        __syncthreads();   // prev O-gemm done with QP/Vs; Kst visible on first iter
#pragma unroll
        for (int u = 0; u < 8; u++) {
            int sid = tid + 128 * u;
            int r = sid >> 4, c4 = sid & 15;
            float4 v = *(const float4*)(g_Q + (colbase + r) * HH + 4 * c4);
            int col = 4 * ((r >> 2) ^ c4) + (r & 3);
            QP[4 * c4 + 0][col] = v.x;
            QP[4 * c4 + 1][col] = v.y;
            QP[4 * c4 + 2][col] = v.z;
            QP[4 * c4 + 3][col] = v.w;
            float4 w = *(const float4*)(g_V + (colbase + r) * HH + 4 * c4);
            *(float4*)&Vs[r][4 * c4] = w;
        }
        __syncthreads();

        // ---- S = k-rows x q-cols, outer product over h, f32x2 packed ----
        ull s2[4][4];
#pragma unroll
        for (int p = 0; p < 4; p++)
#pragma unroll
            for (int j = 0; j < 4; j++) s2[p][j] = zz;
#pragma unroll 1
        for (int k4 = 0; k4 < 16; k4++) {
            const float* a0p = &Kst[4 * k4][4 * ((2 * ty)     ^ k4)];
            const float* a1p = &Kst[4 * k4][4 * ((2 * ty + 1) ^ k4)];
            const float* bp  = &QP [4 * k4][4 * (tx ^ k4)];
#pragma unroll
            for (int kk = 0; kk < 4; kk++) {
                ulonglong2 A0 = *(const ulonglong2*)(a0p + kk * 64);
                ulonglong2 A1 = *(const ulonglong2*)(a1p + kk * 64);
                float4 bq = *(const float4*)(bp + kk * 64);
                ull b0 = pack2(bq.x, bq.x), b1 = pack2(bq.y, bq.y);
                ull b2 = pack2(bq.z, bq.z), b3 = pack2(bq.w, bq.w);
                ffma2(s2[0][0], A0.x, b0); ffma2(s2[0][1], A0.x, b1);
                ffma2(s2[0][2], A0.x, b2); ffma2(s2[0][3], A0.x, b3);
                ffma2(s2[1][0], A0.y, b0); ffma2(s2[1][1], A0.y, b1);
                ffma2(s2[1][2], A0.y, b2); ffma2(s2[1][3], A0.y, b3);
                ffma2(s2[2][0], A1.x, b0); ffma2(s2[2][1], A1.x, b1);
                ffma2(s2[2][2], A1.x, b2); ffma2(s2[2][3], A1.x, b3);
                ffma2(s2[3][0], A1.y, b0); ffma2(s2[3][1], A1.y, b1);
                ffma2(s2[3][2], A1.y, b2); ffma2(s2[3][3], A1.y, b3);
            }
        }

        float s[8][4];
#pragma unroll
        for (int p = 0; p < 4; p++)
#pragma unroll
            for (int j = 0; j < 4; j++) unpack2(s2[p][j], s[2*p][j], s[2*p+1][j]);

        const float scale = 0.125f;   // 1/sqrt(64)
        if (st == bt) {
#pragma unroll
            for (int i = 0; i < 8; i++)
#pragma unroll
                for (int j = 0; j < 4; j++) {
                    int r = 8 * ty + i, c = 4 * tx + j;
                    s[i][j] = (c <= r) ? s[i][j] * scale : -1e30f;
                }
        } else {
#pragma unroll
            for (int i = 0; i < 8; i++)
#pragma unroll
                for (int j = 0; j < 4; j++) s[i][j] *= scale;
        }

        // ---- online softmax (rows reduced across the 16 tx lanes) ----
        float corr[8];
#pragma unroll
        for (int i = 0; i < 8; i++) {
            float rm = fmaxf(fmaxf(s[i][0], s[i][1]), fmaxf(s[i][2], s[i][3]));
            rm = grpmax16(rm);
            float mnew = fmaxf(mrow[i], rm);
            corr[i] = __expf(mrow[i] - mnew);   // exp(-inf)=0 on first tile
            mrow[i] = mnew;
            float rs = 0.f;
#pragma unroll
            for (int j = 0; j < 4; j++) {
                s[i][j] = __expf(s[i][j] - mnew);
                rs += s[i][j];
            }
            rs = grpsum16(rs);
            lrow[i] = lrow[i] * corr[i] + rs;
        }
#pragma unroll
        for (int p = 0; p < 4; p++) {
            ull c2 = pack2(corr[2*p], corr[2*p+1]);
#pragma unroll
            for (int j = 0; j < 4; j++) mul2(o2[p][j], c2);
        }

        __syncthreads();   // all S-gemm reads of QP done
        // ---- store P^T into QP: element (s,t) at slot (t>>2)^(s>>2) ----
#pragma unroll
        for (int j = 0; j < 4; j++) {
            int prow = 4 * tx + j;
#pragma unroll
            for (int i2 = 0; i2 < 2; i2++) {
                *(float4*)&QP[prow][4 * ((2 * ty + i2) ^ tx)] =
                    make_float4(s[4*i2+0][j], s[4*i2+1][j], s[4*i2+2][j], s[4*i2+3][j]);
            }
        }
        __syncthreads();

        // ---- O += P x V: outer product over s, f32x2 packed ----
#pragma unroll 1
        for (int s4 = 0; s4 < 16; s4++) {
            const float* a0p = &QP[4 * s4][4 * ((2 * ty)     ^ s4)];
            const float* a1p = &QP[4 * s4][4 * ((2 * ty + 1) ^ s4)];
            const float* vp  = &Vs[4 * s4][4 * tx];
#pragma unroll
            for (int kk = 0; kk < 4; kk++) {
                ulonglong2 A0 = *(const ulonglong2*)(a0p + kk * 64);
                ulonglong2 A1 = *(const ulonglong2*)(a1p + kk * 64);
                float4 v = *(const float4*)(vp + kk * 64);
                ull b0 = pack2(v.x, v.x), b1 = pack2(v.y, v.y);
                ull b2 = pack2(v.z, v.z), b3 = pack2(v.w, v.w);
                ffma2(o2[0][0], A0.x, b0); ffma2(o2[0][1], A0.x, b1);
                ffma2(o2[0][2], A0.x, b2); ffma2(o2[0][3], A0.x, b3);
                ffma2(o2[1][0], A0.y, b0); ffma2(o2[1][1], A0.y, b1);
                ffma2(o2[1][2], A0.y, b2); ffma2(o2[1][3], A0.y, b3);
                ffma2(o2[2][0], A1.x, b0); ffma2(o2[2][1], A1.x, b1);
                ffma2(o2[2][2], A1.x, b2); ffma2(o2[2][3], A1.x, b3);
                ffma2(o2[3][0], A1.y, b0); ffma2(o2[3][1], A1.y, b1);
                ffma2(o2[3][2], A1.y, b2); ffma2(o2[3][3], A1.y, b3);
            }
        }
    }

    // ---- normalize and write ----
    float o[8][4];
#pragma unroll
    for (int p = 0; p < 4; p++)
#pragma unroll
        for (int j = 0; j < 4; j++) unpack2(o2[p][j], o[2*p][j], o[2*p+1][j]);
#pragma unroll
    for (int i = 0; i < 8; i++) {
        float inv = 1.0f / lrow[i];
        float4 ov;
        ov.x = o[i][0] * inv; ov.y = o[i][1] * inv;
        ov.z = o[i][2] * inv; ov.w = o[i][3] * inv;
        *(float4*)(out + (rowbase + 8 * ty + i) * HH + 4 * tx) = ov;
    }
}

extern "C" void kernel_launch(void* const* d_in, const int* in_sizes, int n_in,
                              void* d_out, int out_size)
{
    const float* x  = (const float*)d_in[0];
    const float* Wk = (const float*)d_in[1];
    const float* bk = (const float*)d_in[2];
    const float* Wq = (const float*)d_in[3];
    const float* bq = (const float*)d_in[4];
    const float* Wv = (const float*)d_in[5];
    const float* bv = (const float*)d_in[6];
    float* out = (float*)d_out;

    dim3 g1(NROW / 64, 3);    // 256 row-tiles x {k,q,v}
    qkv_kernel<<<g1, 256>>>(x, Wk, bk, Wq, bq, Wv, bv);

    attn_kernel<<<256, 128>>>(out);   // descending-work CTA order
}